// round 5
// baseline (speedup 1.0000x reference)
#include <cuda_runtime.h>
#include <cuda_bf16.h>
#include <math.h>

#define N_NODES 50000
#define N_EDGES 800000
#define F_IN    300
#define HID     128
#define HEADS   4
#define NCLS    9

// ---------------- scratch (device globals; no allocation) ----------------
__device__ int   g_is64;
__device__ int   g_deg[N_NODES];
__device__ int   g_cursor[N_NODES];
__device__ int   g_rowstart[N_NODES + 1];
__device__ int   g_adj_src[N_EDGES];

__device__ float g_A[(size_t)N_NODES * HID];   // gemm output (pre-agg h)
__device__ float g_B[(size_t)N_NODES * HID];   // agg output (post-elu)
__device__ float g_as[(size_t)N_NODES * HEADS];
__device__ float g_ad[(size_t)N_NODES * HEADS];
__device__ float g_h3[(size_t)N_NODES * 12];   // layer3 h padded to 12
__device__ float g_a3s[N_NODES];
__device__ float g_a3d[N_NODES];

// ---------------- edge index decode (int32 vs int64 autodetect) ----------------
__global__ void detect_kernel(const void* ei) {
    __shared__ int any;
    if (threadIdx.x == 0) any = 0;
    __syncthreads();
    const int* p = (const int*)ei;
    for (int i = threadIdx.x; i < 4096; i += 256) {
        if (p[2 * i + 1] != 0) any = 1;
    }
    __syncthreads();
    if (threadIdx.x == 0) g_is64 = (any == 0) ? 1 : 0;
}

__device__ __forceinline__ int edge_src(const void* ei, int e, int is64) {
    if (is64) return (int)((const long long*)ei)[e];
    return ((const int*)ei)[e];
}
__device__ __forceinline__ int edge_dst(const void* ei, int e, int is64) {
    if (is64) return (int)((const long long*)ei)[N_EDGES + e];
    return ((const int*)ei)[N_EDGES + e];
}

// ---------------- CSR build ----------------
__global__ void zero_kernel() {
    int i = blockIdx.x * blockDim.x + threadIdx.x;
    if (i < N_NODES) { g_deg[i] = 0; g_cursor[i] = 0; }
}

__global__ void count_kernel(const void* __restrict__ ei) {
    int e = blockIdx.x * blockDim.x + threadIdx.x;
    int is64 = g_is64;
    if (e < N_EDGES) {
        int dst = edge_dst(ei, e, is64);
        if ((unsigned)dst < (unsigned)N_NODES)
            atomicAdd(&g_deg[dst], 1);
    }
}

// Blocked scan: 1024 threads x ITEMS serial items; 3 barriers total.
__global__ void scan_kernel() {
    __shared__ int wsum[32];
    const int ITEMS = (N_NODES + 1023) / 1024;   // 49
    int t = threadIdx.x, lane = t & 31, warp = t >> 5;
    int base = t * ITEMS;

    int tot = 0;
    #pragma unroll 7
    for (int i = 0; i < ITEMS; i++) {
        int idx = base + i;
        if (idx < N_NODES) tot += g_deg[idx];
    }
    int x = tot;
    #pragma unroll
    for (int off = 1; off < 32; off <<= 1) {
        int y = __shfl_up_sync(0xffffffffu, x, off);
        if (lane >= off) x += y;
    }
    if (lane == 31) wsum[warp] = x;
    __syncthreads();
    if (warp == 0) {
        int wv = wsum[lane];
        #pragma unroll
        for (int off = 1; off < 32; off <<= 1) {
            int y = __shfl_up_sync(0xffffffffu, wv, off);
            if (lane >= off) wv += y;
        }
        wsum[lane] = wv;
    }
    __syncthreads();
    int run = x - tot + ((warp > 0) ? wsum[warp - 1] : 0);  // exclusive prefix
    #pragma unroll 7
    for (int i = 0; i < ITEMS; i++) {
        int idx = base + i;
        if (idx < N_NODES) {
            run += g_deg[idx];
            g_rowstart[idx + 1] = run;
        }
    }
    if (t == 0) g_rowstart[0] = 0;
}

__global__ void fill_kernel(const void* __restrict__ ei) {
    int e = blockIdx.x * blockDim.x + threadIdx.x;
    int is64 = g_is64;
    if (e < N_EDGES) {
        int dst = edge_dst(ei, e, is64);
        int src = edge_src(ei, e, is64);
        if ((unsigned)dst < (unsigned)N_NODES &&
            (unsigned)src < (unsigned)N_NODES) {
            int pos = atomicAdd(&g_cursor[dst], 1);
            int slot = g_rowstart[dst] + pos;
            if ((unsigned)slot < (unsigned)N_EDGES)
                g_adj_src[slot] = src;
        }
    }
}

// ---------------- GEMM: C[M,128] = A[M,K] @ W[K,128] ----------------
// 128x128 tile, 256 threads, 8x8 micro-tile, K-step 8, float4 everywhere.
__global__ __launch_bounds__(256) void gemm128_kernel(
        const float* __restrict__ Ain, const float* __restrict__ W, int M, int K) {
    __shared__ float As[8][128];
    __shared__ float Ws[8][128];
    const float* A = (Ain != nullptr) ? Ain : g_B;
    float* C = g_A;
    int t = threadIdx.x;
    int row0 = blockIdx.x * 128;
    int tx = t & 15;        // col group: cols tx*8 .. tx*8+7
    int ty = t >> 4;        // row group: rows ty*8 .. ty*8+7

    // A load: thread -> (row ar, k offset ak), one float4
    int ar = t >> 1;
    int ak = (t & 1) * 4;
    // W load: thread -> (k row wk, col wc), one float4
    int wk = t >> 5;
    int wc = (t & 31) * 4;

    float acc[8][8];
    #pragma unroll
    for (int i = 0; i < 8; i++)
        #pragma unroll
        for (int j = 0; j < 8; j++) acc[i][j] = 0.f;

    for (int k0 = 0; k0 < K; k0 += 8) {
        // ---- load A tile (128 x 8) ----
        float4 av = make_float4(0.f, 0.f, 0.f, 0.f);
        int gm = row0 + ar;
        if (gm < M) {
            int kb = k0 + ak;
            if (kb + 3 < K) {
                av = *(const float4*)&A[(size_t)gm * K + kb];
            } else {
                float tmp[4] = {0.f, 0.f, 0.f, 0.f};
                #pragma unroll
                for (int i = 0; i < 4; i++)
                    if (kb + i < K) tmp[i] = A[(size_t)gm * K + kb + i];
                av = make_float4(tmp[0], tmp[1], tmp[2], tmp[3]);
            }
        }
        As[ak + 0][ar] = av.x; As[ak + 1][ar] = av.y;
        As[ak + 2][ar] = av.z; As[ak + 3][ar] = av.w;

        // ---- load W tile (8 x 128) ----
        float4 wv = make_float4(0.f, 0.f, 0.f, 0.f);
        int gk = k0 + wk;
        if (gk < K) wv = *(const float4*)&W[(size_t)gk * 128 + wc];
        *(float4*)&Ws[wk][wc] = wv;

        __syncthreads();
        #pragma unroll
        for (int kk = 0; kk < 8; kk++) {
            float a[8], b[8];
            *(float4*)&a[0] = *(const float4*)&As[kk][ty * 8 + 0];
            *(float4*)&a[4] = *(const float4*)&As[kk][ty * 8 + 4];
            *(float4*)&b[0] = *(const float4*)&Ws[kk][tx * 8 + 0];
            *(float4*)&b[4] = *(const float4*)&Ws[kk][tx * 8 + 4];
            #pragma unroll
            for (int i = 0; i < 8; i++)
                #pragma unroll
                for (int j = 0; j < 8; j++)
                    acc[i][j] += a[i] * b[j];
        }
        __syncthreads();
    }

    #pragma unroll
    for (int i = 0; i < 8; i++) {
        int gm = row0 + ty * 8 + i;
        if (gm < M) {
            float4 v0 = make_float4(acc[i][0], acc[i][1], acc[i][2], acc[i][3]);
            float4 v1 = make_float4(acc[i][4], acc[i][5], acc[i][6], acc[i][7]);
            *(float4*)&C[(size_t)gm * 128 + tx * 8 + 0] = v0;
            *(float4*)&C[(size_t)gm * 128 + tx * 8 + 4] = v1;
        }
    }
}

// ---------------- attention logits: a_src/a_dst per (node, head) ----------------
// 256 threads = 2 nodes per block.
__global__ void attn_kernel(const float* __restrict__ att_s, const float* __restrict__ att_d) {
    int t = threadIdx.x;
    int n = blockIdx.x * 2 + (t >> 7);
    if (n >= N_NODES) return;
    int c = t & 127;
    int head = c >> 5, lane = t & 31;
    float v = g_A[(size_t)n * 128 + c];
    float ps = v * att_s[c];
    float pd = v * att_d[c];
    #pragma unroll
    for (int off = 16; off; off >>= 1) {
        ps += __shfl_xor_sync(0xffffffffu, ps, off);
        pd += __shfl_xor_sync(0xffffffffu, pd, off);
    }
    if (lane == 0) {
        g_as[n * HEADS + head] = ps;
        g_ad[n * HEADS + head] = pd;
    }
}

// ---------------- aggregation (128-wide layers), warp per node ----------------
__global__ void agg128_kernel(const float* __restrict__ bias) {
    int t = threadIdx.x;
    int warp = t >> 5, lane = t & 31;
    int n = blockIdx.x * 8 + warp;
    if (n >= N_NODES) return;

    const float* h = g_A;
    float adh = g_ad[n * HEADS + (lane & 3)];
    int s0 = g_rowstart[n], s1 = g_rowstart[n + 1];

    float acc0 = 0.f, acc1 = 0.f, acc2 = 0.f, acc3 = 0.f;
    float ws0 = 0.f, ws1 = 0.f, ws2 = 0.f, ws3 = 0.f;

    for (int base = s0; base < s1; base += 32) {
        int nvalid = min(32, s1 - base);
        int s = (base + lane < s1) ? g_adj_src[base + lane] : 0;
        #pragma unroll
        for (int g = 0; g < 4; g++) {
            int eoff = g * 8 + (lane >> 2);
            int head = lane & 3;
            int esrc = __shfl_sync(0xffffffffu, s, eoff);
            float w = 0.f;
            if (eoff < nvalid) {
                float e = g_as[esrc * HEADS + head] + adh;
                e = (e > 0.f) ? e : 0.2f * e;
                w = __expf(e);
            }
            #pragma unroll
            for (int j = 0; j < 8; j++) {
                int idx = g * 8 + j;
                if (idx >= nvalid) break;
                int ss = __shfl_sync(0xffffffffu, s, idx);
                float w0 = __shfl_sync(0xffffffffu, w, j * 4 + 0);
                float w1 = __shfl_sync(0xffffffffu, w, j * 4 + 1);
                float w2 = __shfl_sync(0xffffffffu, w, j * 4 + 2);
                float w3 = __shfl_sync(0xffffffffu, w, j * 4 + 3);
                const float* row = h + (size_t)ss * 128;
                acc0 += w0 * row[lane];
                acc1 += w1 * row[32 + lane];
                acc2 += w2 * row[64 + lane];
                acc3 += w3 * row[96 + lane];
                ws0 += w0; ws1 += w1; ws2 += w2; ws3 += w3;
            }
        }
    }
    float o0 = (ws0 > 0.f) ? acc0 / ws0 : 0.f;
    float o1 = (ws1 > 0.f) ? acc1 / ws1 : 0.f;
    float o2 = (ws2 > 0.f) ? acc2 / ws2 : 0.f;
    float o3 = (ws3 > 0.f) ? acc3 / ws3 : 0.f;
    o0 += bias[lane];       o1 += bias[32 + lane];
    o2 += bias[64 + lane];  o3 += bias[96 + lane];
    o0 = (o0 > 0.f) ? o0 : expm1f(o0);
    o1 = (o1 > 0.f) ? o1 : expm1f(o1);
    o2 = (o2 > 0.f) ? o2 : expm1f(o2);
    o3 = (o3 > 0.f) ? o3 : expm1f(o3);
    float* out = g_B + (size_t)n * 128;
    out[lane] = o0; out[32 + lane] = o1; out[64 + lane] = o2; out[96 + lane] = o3;
}

// ---------------- layer 3 GEMM (128->9, padded 12) fused with attn dots ----------------
__global__ void gemm3_kernel(const float* __restrict__ W3, const float* __restrict__ as3,
                             const float* __restrict__ ad3) {
    __shared__ float Ws[128 * 12];
    int t = threadIdx.x;   // 256
    for (int i = t; i < 128 * 12; i += 256) {
        int k = i / 12, c = i % 12;
        Ws[i] = (c < NCLS) ? W3[k * NCLS + c] : 0.f;
    }
    __syncthreads();
    int warp = t >> 5, lane = t & 31;
    int n = blockIdx.x * 8 + warp;
    if (n >= N_NODES) return;
    float acc[12];
    #pragma unroll
    for (int c = 0; c < 12; c++) acc[c] = 0.f;
    const float* xr = g_B + (size_t)n * 128;
    #pragma unroll
    for (int kk = 0; kk < 4; kk++) {
        int k = lane + kk * 32;
        float xv = xr[k];
        #pragma unroll
        for (int c = 0; c < 12; c++) acc[c] += xv * Ws[k * 12 + c];
    }
    #pragma unroll
    for (int off = 16; off; off >>= 1)
        #pragma unroll
        for (int c = 0; c < 12; c++) acc[c] += __shfl_xor_sync(0xffffffffu, acc[c], off);
    if (lane == 0) {
        float s = 0.f, d = 0.f;
        #pragma unroll
        for (int c = 0; c < NCLS; c++) { s += acc[c] * as3[c]; d += acc[c] * ad3[c]; }
        g_a3s[n] = s;
        g_a3d[n] = d;
        float* hr = g_h3 + (size_t)n * 12;
        #pragma unroll
        for (int c = 0; c < 12; c++) hr[c] = acc[c];
    }
}

// ---------------- layer 3 aggregation + bias + elu + log_softmax ----------------
__global__ void agg3_kernel(const float* __restrict__ b3, float* __restrict__ out) {
    int t = threadIdx.x;
    int warp = t >> 5, lane = t & 31;
    int n = blockIdx.x * 8 + warp;
    if (n >= N_NODES) return;
    float ad = g_a3d[n];
    int s0 = g_rowstart[n], s1 = g_rowstart[n + 1];
    float4 A0 = make_float4(0, 0, 0, 0), A1 = A0, A2 = A0;
    float ws = 0.f;
    for (int i = s0 + lane; i < s1; i += 32) {
        int s = g_adj_src[i];
        float e = g_a3s[s] + ad;
        e = (e > 0.f) ? e : 0.2f * e;
        float w = __expf(e);
        ws += w;
        const float4* r = (const float4*)(g_h3 + (size_t)s * 12);
        float4 r0 = r[0], r1 = r[1], r2 = r[2];
        A0.x += w * r0.x; A0.y += w * r0.y; A0.z += w * r0.z; A0.w += w * r0.w;
        A1.x += w * r1.x; A1.y += w * r1.y; A1.z += w * r1.z; A1.w += w * r1.w;
        A2.x += w * r2.x;
    }
    #pragma unroll
    for (int off = 16; off; off >>= 1) {
        A0.x += __shfl_xor_sync(0xffffffffu, A0.x, off);
        A0.y += __shfl_xor_sync(0xffffffffu, A0.y, off);
        A0.z += __shfl_xor_sync(0xffffffffu, A0.z, off);
        A0.w += __shfl_xor_sync(0xffffffffu, A0.w, off);
        A1.x += __shfl_xor_sync(0xffffffffu, A1.x, off);
        A1.y += __shfl_xor_sync(0xffffffffu, A1.y, off);
        A1.z += __shfl_xor_sync(0xffffffffu, A1.z, off);
        A1.w += __shfl_xor_sync(0xffffffffu, A1.w, off);
        A2.x += __shfl_xor_sync(0xffffffffu, A2.x, off);
        ws += __shfl_xor_sync(0xffffffffu, ws, off);
    }
    if (lane == 0) {
        float inv = (ws > 0.f) ? 1.f / ws : 0.f;
        float v[9];
        v[0] = A0.x * inv; v[1] = A0.y * inv; v[2] = A0.z * inv; v[3] = A0.w * inv;
        v[4] = A1.x * inv; v[5] = A1.y * inv; v[6] = A1.z * inv; v[7] = A1.w * inv;
        v[8] = A2.x * inv;
        float m = -1e30f;
        #pragma unroll
        for (int c = 0; c < 9; c++) {
            v[c] += b3[c];
            v[c] = (v[c] > 0.f) ? v[c] : expm1f(v[c]);
            m = fmaxf(m, v[c]);
        }
        float se = 0.f;
        #pragma unroll
        for (int c = 0; c < 9; c++) se += __expf(v[c] - m);
        float l = logf(se);
        float* o = out + (size_t)n * 9;
        #pragma unroll
        for (int c = 0; c < 9; c++) o[c] = v[c] - m - l;
    }
}

// ---------------- launch ----------------
extern "C" void kernel_launch(void* const* d_in, const int* in_sizes, int n_in,
                              void* d_out, int out_size) {
    const float* x   = (const float*)d_in[0];
    const void*  ei  = d_in[1];
    const float* W1  = (const float*)d_in[2];
    const float* as1 = (const float*)d_in[3];
    const float* ad1 = (const float*)d_in[4];
    const float* b1  = (const float*)d_in[5];
    const float* W2  = (const float*)d_in[6];
    const float* as2 = (const float*)d_in[7];
    const float* ad2 = (const float*)d_in[8];
    const float* b2  = (const float*)d_in[9];
    const float* W3  = (const float*)d_in[10];
    const float* as3 = (const float*)d_in[11];
    const float* ad3 = (const float*)d_in[12];
    const float* b3  = (const float*)d_in[13];
    float* out = (float*)d_out;

    const int EB = (N_EDGES + 255) / 256;
    const int NB = (N_NODES + 255) / 256;
    const int WB = (N_NODES + 7) / 8;        // warp-per-node grids
    const int GB = (N_NODES + 127) / 128;    // gemm tiles (128 rows)
    const int AB = (N_NODES + 1) / 2;        // attn blocks (2 nodes each)

    // CSR build
    detect_kernel<<<1, 256>>>(ei);
    zero_kernel<<<NB, 256>>>();
    count_kernel<<<EB, 256>>>(ei);
    scan_kernel<<<1, 1024>>>();
    fill_kernel<<<EB, 256>>>(ei);

    // layer 1
    gemm128_kernel<<<GB, 256>>>(x, W1, N_NODES, F_IN);
    attn_kernel<<<AB, 256>>>(as1, ad1);
    agg128_kernel<<<WB, 256>>>(b1);

    // layer 2
    gemm128_kernel<<<GB, 256>>>(nullptr, W2, N_NODES, HID);
    attn_kernel<<<AB, 256>>>(as2, ad2);
    agg128_kernel<<<WB, 256>>>(b2);

    // layer 3
    gemm3_kernel<<<WB, 256>>>(W3, as3, ad3);
    agg3_kernel<<<WB, 256>>>(b3, out);
}

// round 6
// speedup vs baseline: 1.1224x; 1.1224x over previous
#include <cuda_runtime.h>
#include <cuda_bf16.h>
#include <math.h>

#define N_NODES 50000
#define N_EDGES 800000
#define F_IN    300
#define HID     128
#define HEADS   4
#define NCLS    9

#define SCAN_B  256
#define SCAN_NB ((N_NODES + SCAN_B - 1) / SCAN_B)   // 196

// ---------------- scratch (device globals; no allocation) ----------------
__device__ int   g_is64;
__device__ int   g_deg[N_NODES];
__device__ int   g_cursor[N_NODES];
__device__ int   g_rowstart[N_NODES + 1];
__device__ int   g_adj_src[N_EDGES];
__device__ int   g_bsum[SCAN_NB];

__device__ float g_A[(size_t)N_NODES * HID];   // gemm output (pre-agg h)
__device__ float g_B[(size_t)N_NODES * HID];   // agg output (post-elu)
__device__ float g_as[(size_t)N_NODES * HEADS];
__device__ float g_ad[(size_t)N_NODES * HEADS];
__device__ float g_h3[(size_t)N_NODES * 12];   // layer3 h padded to 12
__device__ float g_a3s[N_NODES];
__device__ float g_a3d[N_NODES];

// ---------------- edge index decode (int32 vs int64 autodetect) ----------------
__global__ void detect_kernel(const void* ei) {
    __shared__ int any;
    if (threadIdx.x == 0) any = 0;
    __syncthreads();
    const int* p = (const int*)ei;
    for (int i = threadIdx.x; i < 4096; i += 256) {
        if (p[2 * i + 1] != 0) any = 1;
    }
    __syncthreads();
    if (threadIdx.x == 0) g_is64 = (any == 0) ? 1 : 0;
}

__device__ __forceinline__ int edge_src(const void* ei, int e, int is64) {
    if (is64) return (int)((const long long*)ei)[e];
    return ((const int*)ei)[e];
}
__device__ __forceinline__ int edge_dst(const void* ei, int e, int is64) {
    if (is64) return (int)((const long long*)ei)[N_EDGES + e];
    return ((const int*)ei)[N_EDGES + e];
}

// ---------------- CSR build ----------------
__global__ void zero_kernel() {
    int i = blockIdx.x * blockDim.x + threadIdx.x;
    if (i < N_NODES) { g_deg[i] = 0; g_cursor[i] = 0; }
}

__global__ void count_kernel(const void* __restrict__ ei) {
    int e = blockIdx.x * blockDim.x + threadIdx.x;
    int is64 = g_is64;
    if (e < N_EDGES) {
        int dst = edge_dst(ei, e, is64);
        if ((unsigned)dst < (unsigned)N_NODES)
            atomicAdd(&g_deg[dst], 1);
    }
}

// ---- 3-phase parallel scan ----
// Phase A: per-block sums of deg -> g_bsum
__global__ void scanA_kernel() {
    __shared__ int ws[8];
    int t = threadIdx.x, lane = t & 31, warp = t >> 5;
    int i = blockIdx.x * SCAN_B + t;
    int v = (i < N_NODES) ? g_deg[i] : 0;
    #pragma unroll
    for (int off = 16; off; off >>= 1) v += __shfl_xor_sync(0xffffffffu, v, off);
    if (lane == 0) ws[warp] = v;
    __syncthreads();
    if (t == 0) {
        int s = 0;
        #pragma unroll
        for (int w = 0; w < 8; w++) s += ws[w];
        g_bsum[blockIdx.x] = s;
    }
}

// Phase B: single block exclusive-scans g_bsum (196 values) in place
__global__ void scanB_kernel() {
    __shared__ int ws[8];
    int t = threadIdx.x, lane = t & 31, warp = t >> 5;
    int v = (t < SCAN_NB) ? g_bsum[t] : 0;
    int x = v;
    #pragma unroll
    for (int off = 1; off < 32; off <<= 1) {
        int y = __shfl_up_sync(0xffffffffu, x, off);
        if (lane >= off) x += y;
    }
    if (lane == 31) ws[warp] = x;
    __syncthreads();
    if (warp == 0 && lane < 8) {
        int wv = ws[lane];
        #pragma unroll
        for (int off = 1; off < 8; off <<= 1) {
            int y = __shfl_up_sync(0xffu, wv, off);
            if (lane >= off) wv += y;
        }
        ws[lane] = wv;
    }
    __syncthreads();
    int excl = x - v + ((warp > 0) ? ws[warp - 1] : 0);
    if (t < SCAN_NB) g_bsum[t] = excl;
}

// Phase C: per-block inclusive scan of deg + block offset -> rowstart[i+1]
__global__ void scanC_kernel() {
    __shared__ int ws[8];
    int t = threadIdx.x, lane = t & 31, warp = t >> 5;
    int i = blockIdx.x * SCAN_B + t;
    int v = (i < N_NODES) ? g_deg[i] : 0;
    int x = v;
    #pragma unroll
    for (int off = 1; off < 32; off <<= 1) {
        int y = __shfl_up_sync(0xffffffffu, x, off);
        if (lane >= off) x += y;
    }
    if (lane == 31) ws[warp] = x;
    __syncthreads();
    if (warp == 0 && lane < 8) {
        int wv = ws[lane];
        #pragma unroll
        for (int off = 1; off < 8; off <<= 1) {
            int y = __shfl_up_sync(0xffu, wv, off);
            if (lane >= off) wv += y;
        }
        ws[lane] = wv;
    }
    __syncthreads();
    int incl = x + ((warp > 0) ? ws[warp - 1] : 0) + g_bsum[blockIdx.x];
    if (i < N_NODES) g_rowstart[i + 1] = incl;
    if (i == 0) g_rowstart[0] = 0;
}

__global__ void fill_kernel(const void* __restrict__ ei) {
    int e = blockIdx.x * blockDim.x + threadIdx.x;
    int is64 = g_is64;
    if (e < N_EDGES) {
        int dst = edge_dst(ei, e, is64);
        int src = edge_src(ei, e, is64);
        if ((unsigned)dst < (unsigned)N_NODES &&
            (unsigned)src < (unsigned)N_NODES) {
            int pos = atomicAdd(&g_cursor[dst], 1);
            int slot = g_rowstart[dst] + pos;
            if ((unsigned)slot < (unsigned)N_EDGES)
                g_adj_src[slot] = src;
        }
    }
}

// ---------------- GEMM: C[M,128] = A[M,K] @ W[K,128], fused attn dots ----------------
// 128x128 tile, 256 threads, 8x8 micro-tile, K-step 8, float4 everywhere.
__global__ __launch_bounds__(256) void gemm128_kernel(
        const float* __restrict__ Ain, const float* __restrict__ W, int M, int K,
        const float* __restrict__ att_s, const float* __restrict__ att_d) {
    __shared__ float As[8][128];
    __shared__ float Ws[8][128];
    const float* A = (Ain != nullptr) ? Ain : g_B;
    float* C = g_A;
    int t = threadIdx.x;
    int row0 = blockIdx.x * 128;
    int tx = t & 15;        // col group: cols tx*8 .. tx*8+7
    int ty = t >> 4;        // row group: rows ty*8 .. ty*8+7

    int ar = t >> 1;
    int ak = (t & 1) * 4;
    int wk = t >> 5;
    int wc = (t & 31) * 4;

    float acc[8][8];
    #pragma unroll
    for (int i = 0; i < 8; i++)
        #pragma unroll
        for (int j = 0; j < 8; j++) acc[i][j] = 0.f;

    for (int k0 = 0; k0 < K; k0 += 8) {
        float4 av = make_float4(0.f, 0.f, 0.f, 0.f);
        int gm = row0 + ar;
        if (gm < M) {
            int kb = k0 + ak;
            if (kb + 3 < K) {
                av = *(const float4*)&A[(size_t)gm * K + kb];
            } else {
                float tmp[4] = {0.f, 0.f, 0.f, 0.f};
                #pragma unroll
                for (int i = 0; i < 4; i++)
                    if (kb + i < K) tmp[i] = A[(size_t)gm * K + kb + i];
                av = make_float4(tmp[0], tmp[1], tmp[2], tmp[3]);
            }
        }
        As[ak + 0][ar] = av.x; As[ak + 1][ar] = av.y;
        As[ak + 2][ar] = av.z; As[ak + 3][ar] = av.w;

        float4 wv = make_float4(0.f, 0.f, 0.f, 0.f);
        int gk = k0 + wk;
        if (gk < K) wv = *(const float4*)&W[(size_t)gk * 128 + wc];
        *(float4*)&Ws[wk][wc] = wv;

        __syncthreads();
        #pragma unroll
        for (int kk = 0; kk < 8; kk++) {
            float a[8], b[8];
            *(float4*)&a[0] = *(const float4*)&As[kk][ty * 8 + 0];
            *(float4*)&a[4] = *(const float4*)&As[kk][ty * 8 + 4];
            *(float4*)&b[0] = *(const float4*)&Ws[kk][tx * 8 + 0];
            *(float4*)&b[4] = *(const float4*)&Ws[kk][tx * 8 + 4];
            #pragma unroll
            for (int i = 0; i < 8; i++)
                #pragma unroll
                for (int j = 0; j < 8; j++)
                    acc[i][j] += a[i] * b[j];
        }
        __syncthreads();
    }

    // write C
    #pragma unroll
    for (int i = 0; i < 8; i++) {
        int gm = row0 + ty * 8 + i;
        if (gm < M) {
            float4 v0 = make_float4(acc[i][0], acc[i][1], acc[i][2], acc[i][3]);
            float4 v1 = make_float4(acc[i][4], acc[i][5], acc[i][6], acc[i][7]);
            *(float4*)&C[(size_t)gm * 128 + tx * 8 + 0] = v0;
            *(float4*)&C[(size_t)gm * 128 + tx * 8 + 4] = v1;
        }
    }

    // fused attention logits: this thread's 8 cols (tx*8..tx*8+7) lie in head tx>>2.
    // Reduce partial dots over the 4-thread tx-group (shfl offsets 1,2 stay in-warp:
    // lane = (ty&1)*16 + tx).
    if (att_s != nullptr) {
        float s_att[8], d_att[8];
        #pragma unroll
        for (int j = 0; j < 8; j++) {
            s_att[j] = att_s[tx * 8 + j];
            d_att[j] = att_d[tx * 8 + j];
        }
        #pragma unroll
        for (int i = 0; i < 8; i++) {
            float ps = 0.f, pd = 0.f;
            #pragma unroll
            for (int j = 0; j < 8; j++) {
                ps += acc[i][j] * s_att[j];
                pd += acc[i][j] * d_att[j];
            }
            ps += __shfl_xor_sync(0xffffffffu, ps, 1);
            pd += __shfl_xor_sync(0xffffffffu, pd, 1);
            ps += __shfl_xor_sync(0xffffffffu, ps, 2);
            pd += __shfl_xor_sync(0xffffffffu, pd, 2);
            int gm = row0 + ty * 8 + i;
            if ((tx & 3) == 0 && gm < M) {
                int head = tx >> 2;
                g_as[gm * HEADS + head] = ps;
                g_ad[gm * HEADS + head] = pd;
            }
        }
    }
}

// ---------------- aggregation (128-wide layers), warp per node ----------------
__global__ void agg128_kernel(const float* __restrict__ bias) {
    int t = threadIdx.x;
    int warp = t >> 5, lane = t & 31;
    int n = blockIdx.x * 8 + warp;
    if (n >= N_NODES) return;

    const float* h = g_A;
    float adh = g_ad[n * HEADS + (lane & 3)];
    int s0 = g_rowstart[n], s1 = g_rowstart[n + 1];

    float acc0 = 0.f, acc1 = 0.f, acc2 = 0.f, acc3 = 0.f;
    float ws0 = 0.f, ws1 = 0.f, ws2 = 0.f, ws3 = 0.f;

    for (int base = s0; base < s1; base += 32) {
        int nvalid = min(32, s1 - base);
        int s = (base + lane < s1) ? g_adj_src[base + lane] : 0;
        #pragma unroll
        for (int g = 0; g < 4; g++) {
            int eoff = g * 8 + (lane >> 2);
            int head = lane & 3;
            int esrc = __shfl_sync(0xffffffffu, s, eoff);
            float w = 0.f;
            if (eoff < nvalid) {
                float e = g_as[esrc * HEADS + head] + adh;
                e = (e > 0.f) ? e : 0.2f * e;
                w = __expf(e);
            }
            #pragma unroll
            for (int j = 0; j < 8; j++) {
                int idx = g * 8 + j;
                if (idx >= nvalid) break;
                int ss = __shfl_sync(0xffffffffu, s, idx);
                float w0 = __shfl_sync(0xffffffffu, w, j * 4 + 0);
                float w1 = __shfl_sync(0xffffffffu, w, j * 4 + 1);
                float w2 = __shfl_sync(0xffffffffu, w, j * 4 + 2);
                float w3 = __shfl_sync(0xffffffffu, w, j * 4 + 3);
                const float* row = h + (size_t)ss * 128;
                acc0 += w0 * row[lane];
                acc1 += w1 * row[32 + lane];
                acc2 += w2 * row[64 + lane];
                acc3 += w3 * row[96 + lane];
                ws0 += w0; ws1 += w1; ws2 += w2; ws3 += w3;
            }
        }
    }
    float o0 = (ws0 > 0.f) ? acc0 / ws0 : 0.f;
    float o1 = (ws1 > 0.f) ? acc1 / ws1 : 0.f;
    float o2 = (ws2 > 0.f) ? acc2 / ws2 : 0.f;
    float o3 = (ws3 > 0.f) ? acc3 / ws3 : 0.f;
    o0 += bias[lane];       o1 += bias[32 + lane];
    o2 += bias[64 + lane];  o3 += bias[96 + lane];
    o0 = (o0 > 0.f) ? o0 : expm1f(o0);
    o1 = (o1 > 0.f) ? o1 : expm1f(o1);
    o2 = (o2 > 0.f) ? o2 : expm1f(o2);
    o3 = (o3 > 0.f) ? o3 : expm1f(o3);
    float* out = g_B + (size_t)n * 128;
    out[lane] = o0; out[32 + lane] = o1; out[64 + lane] = o2; out[96 + lane] = o3;
}

// ---------------- layer 3 GEMM (128->9, padded 12) fused with attn dots ----------------
__global__ void gemm3_kernel(const float* __restrict__ W3, const float* __restrict__ as3,
                             const float* __restrict__ ad3) {
    __shared__ float Ws[128 * 12];
    int t = threadIdx.x;   // 256
    for (int i = t; i < 128 * 12; i += 256) {
        int k = i / 12, c = i % 12;
        Ws[i] = (c < NCLS) ? W3[k * NCLS + c] : 0.f;
    }
    __syncthreads();
    int warp = t >> 5, lane = t & 31;
    int n = blockIdx.x * 8 + warp;
    if (n >= N_NODES) return;
    float acc[12];
    #pragma unroll
    for (int c = 0; c < 12; c++) acc[c] = 0.f;
    const float* xr = g_B + (size_t)n * 128;
    #pragma unroll
    for (int kk = 0; kk < 4; kk++) {
        int k = lane + kk * 32;
        float xv = xr[k];
        #pragma unroll
        for (int c = 0; c < 12; c++) acc[c] += xv * Ws[k * 12 + c];
    }
    #pragma unroll
    for (int off = 16; off; off >>= 1)
        #pragma unroll
        for (int c = 0; c < 12; c++) acc[c] += __shfl_xor_sync(0xffffffffu, acc[c], off);
    if (lane == 0) {
        float s = 0.f, d = 0.f;
        #pragma unroll
        for (int c = 0; c < NCLS; c++) { s += acc[c] * as3[c]; d += acc[c] * ad3[c]; }
        g_a3s[n] = s;
        g_a3d[n] = d;
        float* hr = g_h3 + (size_t)n * 12;
        #pragma unroll
        for (int c = 0; c < 12; c++) hr[c] = acc[c];
    }
}

// ---------------- layer 3 aggregation + bias + elu + log_softmax ----------------
__global__ void agg3_kernel(const float* __restrict__ b3, float* __restrict__ out) {
    int t = threadIdx.x;
    int warp = t >> 5, lane = t & 31;
    int n = blockIdx.x * 8 + warp;
    if (n >= N_NODES) return;
    float ad = g_a3d[n];
    int s0 = g_rowstart[n], s1 = g_rowstart[n + 1];
    float4 A0 = make_float4(0, 0, 0, 0), A1 = A0, A2 = A0;
    float ws = 0.f;
    for (int i = s0 + lane; i < s1; i += 32) {
        int s = g_adj_src[i];
        float e = g_a3s[s] + ad;
        e = (e > 0.f) ? e : 0.2f * e;
        float w = __expf(e);
        ws += w;
        const float4* r = (const float4*)(g_h3 + (size_t)s * 12);
        float4 r0 = r[0], r1 = r[1], r2 = r[2];
        A0.x += w * r0.x; A0.y += w * r0.y; A0.z += w * r0.z; A0.w += w * r0.w;
        A1.x += w * r1.x; A1.y += w * r1.y; A1.z += w * r1.z; A1.w += w * r1.w;
        A2.x += w * r2.x;
    }
    #pragma unroll
    for (int off = 16; off; off >>= 1) {
        A0.x += __shfl_xor_sync(0xffffffffu, A0.x, off);
        A0.y += __shfl_xor_sync(0xffffffffu, A0.y, off);
        A0.z += __shfl_xor_sync(0xffffffffu, A0.z, off);
        A0.w += __shfl_xor_sync(0xffffffffu, A0.w, off);
        A1.x += __shfl_xor_sync(0xffffffffu, A1.x, off);
        A1.y += __shfl_xor_sync(0xffffffffu, A1.y, off);
        A1.z += __shfl_xor_sync(0xffffffffu, A1.z, off);
        A1.w += __shfl_xor_sync(0xffffffffu, A1.w, off);
        A2.x += __shfl_xor_sync(0xffffffffu, A2.x, off);
        ws += __shfl_xor_sync(0xffffffffu, ws, off);
    }
    if (lane == 0) {
        float inv = (ws > 0.f) ? 1.f / ws : 0.f;
        float v[9];
        v[0] = A0.x * inv; v[1] = A0.y * inv; v[2] = A0.z * inv; v[3] = A0.w * inv;
        v[4] = A1.x * inv; v[5] = A1.y * inv; v[6] = A1.z * inv; v[7] = A1.w * inv;
        v[8] = A2.x * inv;
        float m = -1e30f;
        #pragma unroll
        for (int c = 0; c < 9; c++) {
            v[c] += b3[c];
            v[c] = (v[c] > 0.f) ? v[c] : expm1f(v[c]);
            m = fmaxf(m, v[c]);
        }
        float se = 0.f;
        #pragma unroll
        for (int c = 0; c < 9; c++) se += __expf(v[c] - m);
        float l = logf(se);
        float* o = out + (size_t)n * 9;
        #pragma unroll
        for (int c = 0; c < 9; c++) o[c] = v[c] - m - l;
    }
}

// ---------------- launch ----------------
extern "C" void kernel_launch(void* const* d_in, const int* in_sizes, int n_in,
                              void* d_out, int out_size) {
    const float* x   = (const float*)d_in[0];
    const void*  ei  = d_in[1];
    const float* W1  = (const float*)d_in[2];
    const float* as1 = (const float*)d_in[3];
    const float* ad1 = (const float*)d_in[4];
    const float* b1  = (const float*)d_in[5];
    const float* W2  = (const float*)d_in[6];
    const float* as2 = (const float*)d_in[7];
    const float* ad2 = (const float*)d_in[8];
    const float* b2  = (const float*)d_in[9];
    const float* W3  = (const float*)d_in[10];
    const float* as3 = (const float*)d_in[11];
    const float* ad3 = (const float*)d_in[12];
    const float* b3  = (const float*)d_in[13];
    float* out = (float*)d_out;

    const int EB = (N_EDGES + 255) / 256;
    const int NB = (N_NODES + 255) / 256;
    const int WB = (N_NODES + 7) / 8;        // warp-per-node grids
    const int GB = (N_NODES + 127) / 128;    // gemm tiles (128 rows)

    // CSR build
    detect_kernel<<<1, 256>>>(ei);
    zero_kernel<<<NB, 256>>>();
    count_kernel<<<EB, 256>>>(ei);
    scanA_kernel<<<SCAN_NB, SCAN_B>>>();
    scanB_kernel<<<1, 256>>>();
    scanC_kernel<<<SCAN_NB, SCAN_B>>>();
    fill_kernel<<<EB, 256>>>(ei);

    // layer 1 (attn fused into gemm epilogue)
    gemm128_kernel<<<GB, 256>>>(x, W1, N_NODES, F_IN, as1, ad1);
    agg128_kernel<<<WB, 256>>>(b1);

    // layer 2
    gemm128_kernel<<<GB, 256>>>(nullptr, W2, N_NODES, HID, as2, ad2);
    agg128_kernel<<<WB, 256>>>(b2);

    // layer 3
    gemm3_kernel<<<WB, 256>>>(W3, as3, ad3);
    agg3_kernel<<<WB, 256>>>(b3, out);
}

// round 7
// speedup vs baseline: 1.3082x; 1.1655x over previous
#include <cuda_runtime.h>
#include <cuda_bf16.h>
#include <math.h>

#define N_NODES 50000
#define N_EDGES 800000
#define F_IN    300
#define HID     128
#define HEADS   4
#define NCLS    9

#define SCAN_B  256
#define SCAN_NB ((N_NODES + SCAN_B - 1) / SCAN_B)   // 196

// ---------------- scratch (device globals; no allocation) ----------------
__device__ int   g_is64;
__device__ int   g_deg[N_NODES];
__device__ int   g_cursor[N_NODES];
__device__ int   g_rowstart[N_NODES + 1];
__device__ int   g_adj_src[N_EDGES];
__device__ int   g_bsum[SCAN_NB];

__device__ float g_A[(size_t)N_NODES * HID];   // gemm output (pre-agg h)
__device__ float g_B[(size_t)N_NODES * HID];   // agg output (post-elu)
__device__ float g_as[(size_t)N_NODES * HEADS];
__device__ float g_ad[(size_t)N_NODES * HEADS];
__device__ float g_h3[(size_t)N_NODES * 12];   // layer3 h padded to 12
__device__ float g_a3s[N_NODES];
__device__ float g_a3d[N_NODES];

// ---------------- helpers ----------------
__device__ __forceinline__ unsigned f2tf32(float x) {
    unsigned r;
    asm("cvt.rna.tf32.f32 %0, %1;" : "=r"(r) : "f"(x));
    return r;
}

#define MMA_TF32(c, a, b0, b1)                                                        \
    asm volatile("mma.sync.aligned.m16n8k8.row.col.f32.tf32.tf32.f32 "                \
                 "{%0,%1,%2,%3}, {%4,%5,%6,%7}, {%8,%9}, {%0,%1,%2,%3};"              \
                 : "+f"((c)[0]), "+f"((c)[1]), "+f"((c)[2]), "+f"((c)[3])             \
                 : "r"((a)[0]), "r"((a)[1]), "r"((a)[2]), "r"((a)[3]),                \
                   "r"(b0), "r"(b1))

__device__ __forceinline__ int edge_src(const void* ei, int e, int is64) {
    if (is64) return (int)((const long long*)ei)[e];
    return ((const int*)ei)[e];
}
__device__ __forceinline__ int edge_dst(const void* ei, int e, int is64) {
    if (is64) return (int)((const long long*)ei)[N_EDGES + e];
    return ((const int*)ei)[N_EDGES + e];
}

// ---------------- CSR build ----------------
// zero deg; block 0 also autodetects edge dtype (int32 vs int64).
__global__ void zero_kernel(const void* ei) {
    int i = blockIdx.x * blockDim.x + threadIdx.x;
    if (i < N_NODES) g_deg[i] = 0;
    if (blockIdx.x == 0) {
        __shared__ int any;
        if (threadIdx.x == 0) any = 0;
        __syncthreads();
        const int* p = (const int*)ei;
        for (int k = threadIdx.x; k < 4096; k += 256)
            if (p[2 * k + 1] != 0) any = 1;
        __syncthreads();
        if (threadIdx.x == 0) g_is64 = (any == 0) ? 1 : 0;
    }
}

__global__ void count_kernel(const void* __restrict__ ei) {
    int e = blockIdx.x * blockDim.x + threadIdx.x;
    int is64 = g_is64;
    if (e < N_EDGES) {
        int dst = edge_dst(ei, e, is64);
        if ((unsigned)dst < (unsigned)N_NODES)
            atomicAdd(&g_deg[dst], 1);
    }
}

__global__ void scanA_kernel() {
    __shared__ int ws[8];
    int t = threadIdx.x, lane = t & 31, warp = t >> 5;
    int i = blockIdx.x * SCAN_B + t;
    int v = (i < N_NODES) ? g_deg[i] : 0;
    #pragma unroll
    for (int off = 16; off; off >>= 1) v += __shfl_xor_sync(0xffffffffu, v, off);
    if (lane == 0) ws[warp] = v;
    __syncthreads();
    if (t == 0) {
        int s = 0;
        #pragma unroll
        for (int w = 0; w < 8; w++) s += ws[w];
        g_bsum[blockIdx.x] = s;
    }
}

__global__ void scanB_kernel() {
    __shared__ int ws[8];
    int t = threadIdx.x, lane = t & 31, warp = t >> 5;
    int v = (t < SCAN_NB) ? g_bsum[t] : 0;
    int x = v;
    #pragma unroll
    for (int off = 1; off < 32; off <<= 1) {
        int y = __shfl_up_sync(0xffffffffu, x, off);
        if (lane >= off) x += y;
    }
    if (lane == 31) ws[warp] = x;
    __syncthreads();
    if (warp == 0 && lane < 8) {
        int wv = ws[lane];
        #pragma unroll
        for (int off = 1; off < 8; off <<= 1) {
            int y = __shfl_up_sync(0xffu, wv, off);
            if (lane >= off) wv += y;
        }
        ws[lane] = wv;
    }
    __syncthreads();
    int excl = x - v + ((warp > 0) ? ws[warp - 1] : 0);
    if (t < SCAN_NB) g_bsum[t] = excl;
}

// rowstart[i+1] = inclusive; cursor[i] = exclusive (fill's atomic base)
__global__ void scanC_kernel() {
    __shared__ int ws[8];
    int t = threadIdx.x, lane = t & 31, warp = t >> 5;
    int i = blockIdx.x * SCAN_B + t;
    int v = (i < N_NODES) ? g_deg[i] : 0;
    int x = v;
    #pragma unroll
    for (int off = 1; off < 32; off <<= 1) {
        int y = __shfl_up_sync(0xffffffffu, x, off);
        if (lane >= off) x += y;
    }
    if (lane == 31) ws[warp] = x;
    __syncthreads();
    if (warp == 0 && lane < 8) {
        int wv = ws[lane];
        #pragma unroll
        for (int off = 1; off < 8; off <<= 1) {
            int y = __shfl_up_sync(0xffu, wv, off);
            if (lane >= off) wv += y;
        }
        ws[lane] = wv;
    }
    __syncthreads();
    int incl = x + ((warp > 0) ? ws[warp - 1] : 0) + g_bsum[blockIdx.x];
    if (i < N_NODES) {
        g_rowstart[i + 1] = incl;
        g_cursor[i] = incl - v;
    }
    if (i == 0) g_rowstart[0] = 0;
}

__global__ void fill_kernel(const void* __restrict__ ei) {
    int e = blockIdx.x * blockDim.x + threadIdx.x;
    int is64 = g_is64;
    if (e < N_EDGES) {
        int dst = edge_dst(ei, e, is64);
        int src = edge_src(ei, e, is64);
        if ((unsigned)dst < (unsigned)N_NODES &&
            (unsigned)src < (unsigned)N_NODES) {
            int slot = atomicAdd(&g_cursor[dst], 1);
            if ((unsigned)slot < (unsigned)N_EDGES)
                g_adj_src[slot] = src;
        }
    }
}

// ---------------- GEMM (tf32 split, tensor cores): C[M,128]=A[M,K]@W[K,128] ----------------
// 128x128x16 block tile, 8 warps, warp tile 32x64 (2x8 m16n8k8 atoms).
// 3-term compensation: hi*hi + hi*lo + lo*hi  (fp32-grade accuracy).
// Fused per-head attention dots in epilogue.
__global__ __launch_bounds__(256) void gemm_tf32_kernel(
        const float* __restrict__ Ain, const float* __restrict__ W, int M, int K,
        const float* __restrict__ att_s, const float* __restrict__ att_d) {
    __shared__ unsigned As_hi[16][132], As_lo[16][132];
    __shared__ unsigned Ws_hi[16][132], Ws_lo[16][132];
    const float* A = (Ain != nullptr) ? Ain : g_B;
    float* C = g_A;

    int t = threadIdx.x;
    int lane = t & 31, warp = t >> 5;
    int wr = warp >> 1;       // 0..3 : rows wr*32
    int wc = warp & 1;        // 0..1 : cols wc*64
    int row0 = blockIdx.x * 128;
    int q = lane & 3, g = lane >> 2;

    float acc[2][8][4];
    #pragma unroll
    for (int ma = 0; ma < 2; ma++)
        #pragma unroll
        for (int na = 0; na < 8; na++)
            #pragma unroll
            for (int r = 0; r < 4; r++) acc[ma][na][r] = 0.f;

    for (int k0 = 0; k0 < K; k0 += 16) {
        // ---- A tile: 128 rows x 16 k ----
        #pragma unroll
        for (int i = 0; i < 2; i++) {
            int row = t >> 1;
            int kg = (t & 1) * 2 + i;
            int gm = row0 + row;
            float v[4] = {0.f, 0.f, 0.f, 0.f};
            if (gm < M) {
                int kb = k0 + kg * 4;
                if (kb + 3 < K) {
                    float4 f = *(const float4*)&A[(size_t)gm * K + kb];
                    v[0] = f.x; v[1] = f.y; v[2] = f.z; v[3] = f.w;
                } else {
                    #pragma unroll
                    for (int j = 0; j < 4; j++)
                        if (kb + j < K) v[j] = A[(size_t)gm * K + kb + j];
                }
            }
            #pragma unroll
            for (int j = 0; j < 4; j++) {
                unsigned hi = f2tf32(v[j]);
                As_hi[kg * 4 + j][row] = hi;
                As_lo[kg * 4 + j][row] = f2tf32(v[j] - __uint_as_float(hi));
            }
        }
        // ---- W tile: 16 k x 128 n ----
        #pragma unroll
        for (int i = 0; i < 2; i++) {
            int k = (t >> 5) + i * 8;
            int n = (t & 31) * 4;
            float v[4] = {0.f, 0.f, 0.f, 0.f};
            int gk = k0 + k;
            if (gk < K) {
                float4 f = *(const float4*)&W[(size_t)gk * 128 + n];
                v[0] = f.x; v[1] = f.y; v[2] = f.z; v[3] = f.w;
            }
            #pragma unroll
            for (int j = 0; j < 4; j++) {
                unsigned hi = f2tf32(v[j]);
                Ws_hi[k][n + j] = hi;
                Ws_lo[k][n + j] = f2tf32(v[j] - __uint_as_float(hi));
            }
        }
        __syncthreads();

        #pragma unroll
        for (int ks = 0; ks < 16; ks += 8) {
            unsigned ah[2][4], al[2][4];
            #pragma unroll
            for (int ma = 0; ma < 2; ma++) {
                int ra = wr * 32 + ma * 16 + g;
                int ka = ks + q;
                ah[ma][0] = As_hi[ka][ra];     ah[ma][1] = As_hi[ka][ra + 8];
                ah[ma][2] = As_hi[ka + 4][ra]; ah[ma][3] = As_hi[ka + 4][ra + 8];
                al[ma][0] = As_lo[ka][ra];     al[ma][1] = As_lo[ka][ra + 8];
                al[ma][2] = As_lo[ka + 4][ra]; al[ma][3] = As_lo[ka + 4][ra + 8];
            }
            #pragma unroll
            for (int na = 0; na < 8; na++) {
                int cb = wc * 64 + na * 8 + g;
                int kb = ks + q;
                unsigned bh0 = Ws_hi[kb][cb], bh1 = Ws_hi[kb + 4][cb];
                unsigned bl0 = Ws_lo[kb][cb], bl1 = Ws_lo[kb + 4][cb];
                #pragma unroll
                for (int ma = 0; ma < 2; ma++) {
                    MMA_TF32(acc[ma][na], ah[ma], bh0, bh1);
                    MMA_TF32(acc[ma][na], ah[ma], bl0, bl1);
                    MMA_TF32(acc[ma][na], al[ma], bh0, bh1);
                }
            }
        }
        __syncthreads();
    }

    // ---- store C ----
    #pragma unroll
    for (int ma = 0; ma < 2; ma++) {
        int gml = row0 + wr * 32 + ma * 16 + g;
        int gmh = gml + 8;
        #pragma unroll
        for (int na = 0; na < 8; na++) {
            int col = wc * 64 + na * 8 + 2 * q;
            if (gml < M)
                *(float2*)&C[(size_t)gml * 128 + col] = make_float2(acc[ma][na][0], acc[ma][na][1]);
            if (gmh < M)
                *(float2*)&C[(size_t)gmh * 128 + col] = make_float2(acc[ma][na][2], acc[ma][na][3]);
        }
    }

    // ---- fused attention logits ----
    if (att_s != nullptr) {
        #pragma unroll
        for (int ma = 0; ma < 2; ma++) {
            #pragma unroll
            for (int r = 0; r < 2; r++) {
                int gm = row0 + wr * 32 + ma * 16 + g + r * 8;
                #pragma unroll
                for (int hl = 0; hl < 2; hl++) {
                    float ps = 0.f, pd = 0.f;
                    #pragma unroll
                    for (int nn = 0; nn < 4; nn++) {
                        int na = hl * 4 + nn;
                        int col = wc * 64 + na * 8 + 2 * q;
                        float cA = acc[ma][na][r * 2 + 0];
                        float cB = acc[ma][na][r * 2 + 1];
                        ps += cA * att_s[col] + cB * att_s[col + 1];
                        pd += cA * att_d[col] + cB * att_d[col + 1];
                    }
                    ps += __shfl_xor_sync(0xffffffffu, ps, 1);
                    pd += __shfl_xor_sync(0xffffffffu, pd, 1);
                    ps += __shfl_xor_sync(0xffffffffu, ps, 2);
                    pd += __shfl_xor_sync(0xffffffffu, pd, 2);
                    if (q == 0 && gm < M) {
                        int head = wc * 2 + hl;
                        g_as[gm * HEADS + head] = ps;
                        g_ad[gm * HEADS + head] = pd;
                    }
                }
            }
        }
    }
}

// ---------------- aggregation (128-wide layers), warp per node ----------------
__global__ void agg128_kernel(const float* __restrict__ bias) {
    int t = threadIdx.x;
    int warp = t >> 5, lane = t & 31;
    int n = blockIdx.x * 8 + warp;
    if (n >= N_NODES) return;

    const float* h = g_A;
    float adh = g_ad[n * HEADS + (lane & 3)];
    int s0 = g_rowstart[n], s1 = g_rowstart[n + 1];

    float acc0 = 0.f, acc1 = 0.f, acc2 = 0.f, acc3 = 0.f;
    float ws0 = 0.f, ws1 = 0.f, ws2 = 0.f, ws3 = 0.f;

    for (int base = s0; base < s1; base += 32) {
        int nvalid = min(32, s1 - base);
        int s = (base + lane < s1) ? g_adj_src[base + lane] : 0;
        #pragma unroll
        for (int g = 0; g < 4; g++) {
            int eoff = g * 8 + (lane >> 2);
            int head = lane & 3;
            int esrc = __shfl_sync(0xffffffffu, s, eoff);
            float w = 0.f;
            if (eoff < nvalid) {
                float e = g_as[esrc * HEADS + head] + adh;
                e = (e > 0.f) ? e : 0.2f * e;
                w = __expf(e);
            }
            #pragma unroll
            for (int j = 0; j < 8; j++) {
                int idx = g * 8 + j;
                if (idx >= nvalid) break;
                int ss = __shfl_sync(0xffffffffu, s, idx);
                float w0 = __shfl_sync(0xffffffffu, w, j * 4 + 0);
                float w1 = __shfl_sync(0xffffffffu, w, j * 4 + 1);
                float w2 = __shfl_sync(0xffffffffu, w, j * 4 + 2);
                float w3 = __shfl_sync(0xffffffffu, w, j * 4 + 3);
                const float* row = h + (size_t)ss * 128;
                acc0 += w0 * row[lane];
                acc1 += w1 * row[32 + lane];
                acc2 += w2 * row[64 + lane];
                acc3 += w3 * row[96 + lane];
                ws0 += w0; ws1 += w1; ws2 += w2; ws3 += w3;
            }
        }
    }
    float o0 = (ws0 > 0.f) ? acc0 / ws0 : 0.f;
    float o1 = (ws1 > 0.f) ? acc1 / ws1 : 0.f;
    float o2 = (ws2 > 0.f) ? acc2 / ws2 : 0.f;
    float o3 = (ws3 > 0.f) ? acc3 / ws3 : 0.f;
    o0 += bias[lane];       o1 += bias[32 + lane];
    o2 += bias[64 + lane];  o3 += bias[96 + lane];
    o0 = (o0 > 0.f) ? o0 : expm1f(o0);
    o1 = (o1 > 0.f) ? o1 : expm1f(o1);
    o2 = (o2 > 0.f) ? o2 : expm1f(o2);
    o3 = (o3 > 0.f) ? o3 : expm1f(o3);
    float* out = g_B + (size_t)n * 128;
    out[lane] = o0; out[32 + lane] = o1; out[64 + lane] = o2; out[96 + lane] = o3;
}

// ---------------- layer 3 GEMM (128->9, padded 12) fused with attn dots ----------------
__global__ void gemm3_kernel(const float* __restrict__ W3, const float* __restrict__ as3,
                             const float* __restrict__ ad3) {
    __shared__ float Ws[128 * 12];
    int t = threadIdx.x;   // 256
    for (int i = t; i < 128 * 12; i += 256) {
        int k = i / 12, c = i % 12;
        Ws[i] = (c < NCLS) ? W3[k * NCLS + c] : 0.f;
    }
    __syncthreads();
    int warp = t >> 5, lane = t & 31;
    int n = blockIdx.x * 8 + warp;
    if (n >= N_NODES) return;
    float acc[12];
    #pragma unroll
    for (int c = 0; c < 12; c++) acc[c] = 0.f;
    const float* xr = g_B + (size_t)n * 128;
    #pragma unroll
    for (int kk = 0; kk < 4; kk++) {
        int k = lane + kk * 32;
        float xv = xr[k];
        #pragma unroll
        for (int c = 0; c < 12; c++) acc[c] += xv * Ws[k * 12 + c];
    }
    #pragma unroll
    for (int off = 16; off; off >>= 1)
        #pragma unroll
        for (int c = 0; c < 12; c++) acc[c] += __shfl_xor_sync(0xffffffffu, acc[c], off);
    if (lane == 0) {
        float s = 0.f, d = 0.f;
        #pragma unroll
        for (int c = 0; c < NCLS; c++) { s += acc[c] * as3[c]; d += acc[c] * ad3[c]; }
        g_a3s[n] = s;
        g_a3d[n] = d;
        float* hr = g_h3 + (size_t)n * 12;
        #pragma unroll
        for (int c = 0; c < 12; c++) hr[c] = acc[c];
    }
}

// ---------------- layer 3 aggregation + bias + elu + log_softmax ----------------
__global__ void agg3_kernel(const float* __restrict__ b3, float* __restrict__ out) {
    int t = threadIdx.x;
    int warp = t >> 5, lane = t & 31;
    int n = blockIdx.x * 8 + warp;
    if (n >= N_NODES) return;
    float ad = g_a3d[n];
    int s0 = g_rowstart[n], s1 = g_rowstart[n + 1];
    float4 A0 = make_float4(0, 0, 0, 0), A1 = A0, A2 = A0;
    float ws = 0.f;
    for (int i = s0 + lane; i < s1; i += 32) {
        int s = g_adj_src[i];
        float e = g_a3s[s] + ad;
        e = (e > 0.f) ? e : 0.2f * e;
        float w = __expf(e);
        ws += w;
        const float4* r = (const float4*)(g_h3 + (size_t)s * 12);
        float4 r0 = r[0], r1 = r[1], r2 = r[2];
        A0.x += w * r0.x; A0.y += w * r0.y; A0.z += w * r0.z; A0.w += w * r0.w;
        A1.x += w * r1.x; A1.y += w * r1.y; A1.z += w * r1.z; A1.w += w * r1.w;
        A2.x += w * r2.x;
    }
    #pragma unroll
    for (int off = 16; off; off >>= 1) {
        A0.x += __shfl_xor_sync(0xffffffffu, A0.x, off);
        A0.y += __shfl_xor_sync(0xffffffffu, A0.y, off);
        A0.z += __shfl_xor_sync(0xffffffffu, A0.z, off);
        A0.w += __shfl_xor_sync(0xffffffffu, A0.w, off);
        A1.x += __shfl_xor_sync(0xffffffffu, A1.x, off);
        A1.y += __shfl_xor_sync(0xffffffffu, A1.y, off);
        A1.z += __shfl_xor_sync(0xffffffffu, A1.z, off);
        A1.w += __shfl_xor_sync(0xffffffffu, A1.w, off);
        A2.x += __shfl_xor_sync(0xffffffffu, A2.x, off);
        ws += __shfl_xor_sync(0xffffffffu, ws, off);
    }
    if (lane == 0) {
        float inv = (ws > 0.f) ? 1.f / ws : 0.f;
        float v[9];
        v[0] = A0.x * inv; v[1] = A0.y * inv; v[2] = A0.z * inv; v[3] = A0.w * inv;
        v[4] = A1.x * inv; v[5] = A1.y * inv; v[6] = A1.z * inv; v[7] = A1.w * inv;
        v[8] = A2.x * inv;
        float m = -1e30f;
        #pragma unroll
        for (int c = 0; c < 9; c++) {
            v[c] += b3[c];
            v[c] = (v[c] > 0.f) ? v[c] : expm1f(v[c]);
            m = fmaxf(m, v[c]);
        }
        float se = 0.f;
        #pragma unroll
        for (int c = 0; c < 9; c++) se += __expf(v[c] - m);
        float l = logf(se);
        float* o = out + (size_t)n * 9;
        #pragma unroll
        for (int c = 0; c < 9; c++) o[c] = v[c] - m - l;
    }
}

// ---------------- launch ----------------
extern "C" void kernel_launch(void* const* d_in, const int* in_sizes, int n_in,
                              void* d_out, int out_size) {
    const float* x   = (const float*)d_in[0];
    const void*  ei  = d_in[1];
    const float* W1  = (const float*)d_in[2];
    const float* as1 = (const float*)d_in[3];
    const float* ad1 = (const float*)d_in[4];
    const float* b1  = (const float*)d_in[5];
    const float* W2  = (const float*)d_in[6];
    const float* as2 = (const float*)d_in[7];
    const float* ad2 = (const float*)d_in[8];
    const float* b2  = (const float*)d_in[9];
    const float* W3  = (const float*)d_in[10];
    const float* as3 = (const float*)d_in[11];
    const float* ad3 = (const float*)d_in[12];
    const float* b3  = (const float*)d_in[13];
    float* out = (float*)d_out;

    const int EB = (N_EDGES + 255) / 256;
    const int WB = (N_NODES + 7) / 8;        // warp-per-node grids
    const int GB = (N_NODES + 127) / 128;    // gemm tiles (128 rows)

    // CSR build
    zero_kernel<<<SCAN_NB, 256>>>(ei);
    count_kernel<<<EB, 256>>>(ei);
    scanA_kernel<<<SCAN_NB, SCAN_B>>>();
    scanB_kernel<<<1, 256>>>();
    scanC_kernel<<<SCAN_NB, SCAN_B>>>();
    fill_kernel<<<EB, 256>>>(ei);

    // layer 1 (attn fused into gemm epilogue)
    gemm_tf32_kernel<<<GB, 256>>>(x, W1, N_NODES, F_IN, as1, ad1);
    agg128_kernel<<<WB, 256>>>(b1);

    // layer 2
    gemm_tf32_kernel<<<GB, 256>>>(nullptr, W2, N_NODES, HID, as2, ad2);
    agg128_kernel<<<WB, 256>>>(b2);

    // layer 3
    gemm3_kernel<<<WB, 256>>>(W3, as3, ad3);
    agg3_kernel<<<WB, 256>>>(b3, out);
}

// round 8
// speedup vs baseline: 1.3150x; 1.0052x over previous
#include <cuda_runtime.h>
#include <cuda_bf16.h>
#include <math.h>

#define N_NODES 50000
#define N_EDGES 800000
#define F_IN    300
#define HID     128
#define HEADS   4
#define NCLS    9

#define SCAN_B  256
#define SCAN_NB ((N_NODES + SCAN_B - 1) / SCAN_B)   // 196

// ---------------- scratch (device globals; no allocation) ----------------
__device__ int   g_is64;
__device__ int   g_deg[N_NODES];
__device__ int   g_cursor[N_NODES];
__device__ int   g_rowstart[N_NODES + 1];
__device__ int   g_adj_src[N_EDGES];
__device__ int   g_adj_dst[N_EDGES];
__device__ int   g_bsum[SCAN_NB];

__device__ float g_A[(size_t)N_NODES * HID];   // gemm output (pre-agg h)
__device__ float g_B[(size_t)N_NODES * HID];   // agg output (post-elu)
__device__ float g_as[(size_t)N_NODES * HEADS];
__device__ float g_ad[(size_t)N_NODES * HEADS];
__device__ float g_w[(size_t)N_EDGES * HEADS]; // per-edge softmax numerators
__device__ float g_w3[N_EDGES];
__device__ float g_h3[(size_t)N_NODES * 12];   // layer3 h padded to 12
__device__ float g_a3s[N_NODES];
__device__ float g_a3d[N_NODES];

// ---------------- helpers ----------------
__device__ __forceinline__ unsigned f2tf32(float x) {
    unsigned r;
    asm("cvt.rna.tf32.f32 %0, %1;" : "=r"(r) : "f"(x));
    return r;
}

#define MMA_TF32(c, a, b0, b1)                                                        \
    asm volatile("mma.sync.aligned.m16n8k8.row.col.f32.tf32.tf32.f32 "                \
                 "{%0,%1,%2,%3}, {%4,%5,%6,%7}, {%8,%9}, {%0,%1,%2,%3};"              \
                 : "+f"((c)[0]), "+f"((c)[1]), "+f"((c)[2]), "+f"((c)[3])             \
                 : "r"((a)[0]), "r"((a)[1]), "r"((a)[2]), "r"((a)[3]),                \
                   "r"(b0), "r"(b1))

__device__ __forceinline__ int edge_src(const void* ei, int e, int is64) {
    if (is64) return (int)((const long long*)ei)[e];
    return ((const int*)ei)[e];
}
__device__ __forceinline__ int edge_dst(const void* ei, int e, int is64) {
    if (is64) return (int)((const long long*)ei)[N_EDGES + e];
    return ((const int*)ei)[N_EDGES + e];
}
__device__ __forceinline__ float lrelu_exp(float e) {
    e = (e > 0.f) ? e : 0.2f * e;
    return __expf(e);
}

// ---------------- CSR build ----------------
__global__ void zero_kernel(const void* ei) {
    int i = blockIdx.x * blockDim.x + threadIdx.x;
    if (i < N_NODES) g_deg[i] = 0;
    if (blockIdx.x == 0) {
        __shared__ int any;
        if (threadIdx.x == 0) any = 0;
        __syncthreads();
        const int* p = (const int*)ei;
        for (int k = threadIdx.x; k < 4096; k += 256)
            if (p[2 * k + 1] != 0) any = 1;
        __syncthreads();
        if (threadIdx.x == 0) g_is64 = (any == 0) ? 1 : 0;
    }
}

__global__ void count_kernel(const void* __restrict__ ei) {
    int e = blockIdx.x * blockDim.x + threadIdx.x;
    int is64 = g_is64;
    if (e < N_EDGES) {
        int dst = edge_dst(ei, e, is64);
        if ((unsigned)dst < (unsigned)N_NODES)
            atomicAdd(&g_deg[dst], 1);
    }
}

__global__ void scanA_kernel() {
    __shared__ int ws[8];
    int t = threadIdx.x, lane = t & 31, warp = t >> 5;
    int i = blockIdx.x * SCAN_B + t;
    int v = (i < N_NODES) ? g_deg[i] : 0;
    #pragma unroll
    for (int off = 16; off; off >>= 1) v += __shfl_xor_sync(0xffffffffu, v, off);
    if (lane == 0) ws[warp] = v;
    __syncthreads();
    if (t == 0) {
        int s = 0;
        #pragma unroll
        for (int w = 0; w < 8; w++) s += ws[w];
        g_bsum[blockIdx.x] = s;
    }
}

__global__ void scanB_kernel() {
    __shared__ int ws[8];
    int t = threadIdx.x, lane = t & 31, warp = t >> 5;
    int v = (t < SCAN_NB) ? g_bsum[t] : 0;
    int x = v;
    #pragma unroll
    for (int off = 1; off < 32; off <<= 1) {
        int y = __shfl_up_sync(0xffffffffu, x, off);
        if (lane >= off) x += y;
    }
    if (lane == 31) ws[warp] = x;
    __syncthreads();
    if (warp == 0 && lane < 8) {
        int wv = ws[lane];
        #pragma unroll
        for (int off = 1; off < 8; off <<= 1) {
            int y = __shfl_up_sync(0xffu, wv, off);
            if (lane >= off) wv += y;
        }
        ws[lane] = wv;
    }
    __syncthreads();
    int excl = x - v + ((warp > 0) ? ws[warp - 1] : 0);
    if (t < SCAN_NB) g_bsum[t] = excl;
}

__global__ void scanC_kernel() {
    __shared__ int ws[8];
    int t = threadIdx.x, lane = t & 31, warp = t >> 5;
    int i = blockIdx.x * SCAN_B + t;
    int v = (i < N_NODES) ? g_deg[i] : 0;
    int x = v;
    #pragma unroll
    for (int off = 1; off < 32; off <<= 1) {
        int y = __shfl_up_sync(0xffffffffu, x, off);
        if (lane >= off) x += y;
    }
    if (lane == 31) ws[warp] = x;
    __syncthreads();
    if (warp == 0 && lane < 8) {
        int wv = ws[lane];
        #pragma unroll
        for (int off = 1; off < 8; off <<= 1) {
            int y = __shfl_up_sync(0xffu, wv, off);
            if (lane >= off) wv += y;
        }
        ws[lane] = wv;
    }
    __syncthreads();
    int incl = x + ((warp > 0) ? ws[warp - 1] : 0) + g_bsum[blockIdx.x];
    if (i < N_NODES) {
        g_rowstart[i + 1] = incl;
        g_cursor[i] = incl - v;
    }
    if (i == 0) g_rowstart[0] = 0;
}

__global__ void fill_kernel(const void* __restrict__ ei) {
    int e = blockIdx.x * blockDim.x + threadIdx.x;
    int is64 = g_is64;
    if (e < N_EDGES) {
        int dst = edge_dst(ei, e, is64);
        int src = edge_src(ei, e, is64);
        if ((unsigned)dst < (unsigned)N_NODES &&
            (unsigned)src < (unsigned)N_NODES) {
            int slot = atomicAdd(&g_cursor[dst], 1);
            if ((unsigned)slot < (unsigned)N_EDGES) {
                g_adj_src[slot] = src;
                g_adj_dst[slot] = dst;
            }
        }
    }
}

// ---------------- edge-parallel softmax numerators (layers 1/2) ----------------
__global__ void weight_kernel() {
    int e = blockIdx.x * blockDim.x + threadIdx.x;
    if (e >= N_EDGES) return;
    int src = g_adj_src[e];
    int dst = g_adj_dst[e];
    float4 s = *(const float4*)&g_as[src * HEADS];
    float4 d = *(const float4*)&g_ad[dst * HEADS];
    float4 w;
    w.x = lrelu_exp(s.x + d.x);
    w.y = lrelu_exp(s.y + d.y);
    w.z = lrelu_exp(s.z + d.z);
    w.w = lrelu_exp(s.w + d.w);
    *(float4*)&g_w[(size_t)e * HEADS] = w;
}

__global__ void weight3_kernel() {
    int e = blockIdx.x * blockDim.x + threadIdx.x;
    if (e >= N_EDGES) return;
    g_w3[e] = lrelu_exp(g_a3s[g_adj_src[e]] + g_a3d[g_adj_dst[e]]);
}

// ---------------- GEMM (tf32 split, tensor cores): C[M,128]=A[M,K]@W[K,128] ----------------
__global__ __launch_bounds__(256) void gemm_tf32_kernel(
        const float* __restrict__ Ain, const float* __restrict__ W, int M, int K,
        const float* __restrict__ att_s, const float* __restrict__ att_d) {
    __shared__ unsigned As_hi[16][132], As_lo[16][132];
    __shared__ unsigned Ws_hi[16][132], Ws_lo[16][132];
    const float* A = (Ain != nullptr) ? Ain : g_B;
    float* C = g_A;

    int t = threadIdx.x;
    int lane = t & 31, warp = t >> 5;
    int wr = warp >> 1;
    int wc = warp & 1;
    int row0 = blockIdx.x * 128;
    int q = lane & 3, g = lane >> 2;

    float acc[2][8][4];
    #pragma unroll
    for (int ma = 0; ma < 2; ma++)
        #pragma unroll
        for (int na = 0; na < 8; na++)
            #pragma unroll
            for (int r = 0; r < 4; r++) acc[ma][na][r] = 0.f;

    for (int k0 = 0; k0 < K; k0 += 16) {
        #pragma unroll
        for (int i = 0; i < 2; i++) {
            int row = t >> 1;
            int kg = (t & 1) * 2 + i;
            int gm = row0 + row;
            float v[4] = {0.f, 0.f, 0.f, 0.f};
            if (gm < M) {
                int kb = k0 + kg * 4;
                if (kb + 3 < K) {
                    float4 f = *(const float4*)&A[(size_t)gm * K + kb];
                    v[0] = f.x; v[1] = f.y; v[2] = f.z; v[3] = f.w;
                } else {
                    #pragma unroll
                    for (int j = 0; j < 4; j++)
                        if (kb + j < K) v[j] = A[(size_t)gm * K + kb + j];
                }
            }
            #pragma unroll
            for (int j = 0; j < 4; j++) {
                unsigned hi = f2tf32(v[j]);
                As_hi[kg * 4 + j][row] = hi;
                As_lo[kg * 4 + j][row] = f2tf32(v[j] - __uint_as_float(hi));
            }
        }
        #pragma unroll
        for (int i = 0; i < 2; i++) {
            int k = (t >> 5) + i * 8;
            int n = (t & 31) * 4;
            float v[4] = {0.f, 0.f, 0.f, 0.f};
            int gk = k0 + k;
            if (gk < K) {
                float4 f = *(const float4*)&W[(size_t)gk * 128 + n];
                v[0] = f.x; v[1] = f.y; v[2] = f.z; v[3] = f.w;
            }
            #pragma unroll
            for (int j = 0; j < 4; j++) {
                unsigned hi = f2tf32(v[j]);
                Ws_hi[k][n + j] = hi;
                Ws_lo[k][n + j] = f2tf32(v[j] - __uint_as_float(hi));
            }
        }
        __syncthreads();

        #pragma unroll
        for (int ks = 0; ks < 16; ks += 8) {
            unsigned ah[2][4], al[2][4];
            #pragma unroll
            for (int ma = 0; ma < 2; ma++) {
                int ra = wr * 32 + ma * 16 + g;
                int ka = ks + q;
                ah[ma][0] = As_hi[ka][ra];     ah[ma][1] = As_hi[ka][ra + 8];
                ah[ma][2] = As_hi[ka + 4][ra]; ah[ma][3] = As_hi[ka + 4][ra + 8];
                al[ma][0] = As_lo[ka][ra];     al[ma][1] = As_lo[ka][ra + 8];
                al[ma][2] = As_lo[ka + 4][ra]; al[ma][3] = As_lo[ka + 4][ra + 8];
            }
            #pragma unroll
            for (int na = 0; na < 8; na++) {
                int cb = wc * 64 + na * 8 + g;
                int kb = ks + q;
                unsigned bh0 = Ws_hi[kb][cb], bh1 = Ws_hi[kb + 4][cb];
                unsigned bl0 = Ws_lo[kb][cb], bl1 = Ws_lo[kb + 4][cb];
                #pragma unroll
                for (int ma = 0; ma < 2; ma++) {
                    MMA_TF32(acc[ma][na], ah[ma], bh0, bh1);
                    MMA_TF32(acc[ma][na], ah[ma], bl0, bl1);
                    MMA_TF32(acc[ma][na], al[ma], bh0, bh1);
                }
            }
        }
        __syncthreads();
    }

    #pragma unroll
    for (int ma = 0; ma < 2; ma++) {
        int gml = row0 + wr * 32 + ma * 16 + g;
        int gmh = gml + 8;
        #pragma unroll
        for (int na = 0; na < 8; na++) {
            int col = wc * 64 + na * 8 + 2 * q;
            if (gml < M)
                *(float2*)&C[(size_t)gml * 128 + col] = make_float2(acc[ma][na][0], acc[ma][na][1]);
            if (gmh < M)
                *(float2*)&C[(size_t)gmh * 128 + col] = make_float2(acc[ma][na][2], acc[ma][na][3]);
        }
    }

    if (att_s != nullptr) {
        #pragma unroll
        for (int ma = 0; ma < 2; ma++) {
            #pragma unroll
            for (int r = 0; r < 2; r++) {
                int gm = row0 + wr * 32 + ma * 16 + g + r * 8;
                #pragma unroll
                for (int hl = 0; hl < 2; hl++) {
                    float ps = 0.f, pd = 0.f;
                    #pragma unroll
                    for (int nn = 0; nn < 4; nn++) {
                        int na = hl * 4 + nn;
                        int col = wc * 64 + na * 8 + 2 * q;
                        float cA = acc[ma][na][r * 2 + 0];
                        float cB = acc[ma][na][r * 2 + 1];
                        ps += cA * att_s[col] + cB * att_s[col + 1];
                        pd += cA * att_d[col] + cB * att_d[col + 1];
                    }
                    ps += __shfl_xor_sync(0xffffffffu, ps, 1);
                    pd += __shfl_xor_sync(0xffffffffu, pd, 1);
                    ps += __shfl_xor_sync(0xffffffffu, ps, 2);
                    pd += __shfl_xor_sync(0xffffffffu, pd, 2);
                    if (q == 0 && gm < M) {
                        int head = wc * 2 + hl;
                        g_as[gm * HEADS + head] = ps;
                        g_ad[gm * HEADS + head] = pd;
                    }
                }
            }
        }
    }
}

// ---------------- aggregation (128-wide layers), warp per node, no shfl ----------------
__global__ void agg128_kernel(const float* __restrict__ bias) {
    int t = threadIdx.x;
    int warp = t >> 5, lane = t & 31;
    int n = blockIdx.x * 8 + warp;
    if (n >= N_NODES) return;

    int s0 = g_rowstart[n], s1 = g_rowstart[n + 1];
    float a0 = 0.f, a1 = 0.f, a2 = 0.f, a3 = 0.f;
    float wx = 0.f, wy = 0.f, wz = 0.f, ww = 0.f;

    #pragma unroll 4
    for (int e = s0; e < s1; e++) {
        int src = g_adj_src[e];                       // broadcast load
        float4 w = *(const float4*)&g_w[(size_t)e * HEADS];  // broadcast load
        const float* row = g_A + (size_t)src * 128;
        a0 += w.x * row[lane];
        a1 += w.y * row[32 + lane];
        a2 += w.z * row[64 + lane];
        a3 += w.w * row[96 + lane];
        wx += w.x; wy += w.y; wz += w.z; ww += w.w;
    }

    float o0 = (wx > 0.f) ? a0 / wx : 0.f;
    float o1 = (wy > 0.f) ? a1 / wy : 0.f;
    float o2 = (wz > 0.f) ? a2 / wz : 0.f;
    float o3 = (ww > 0.f) ? a3 / ww : 0.f;
    o0 += bias[lane];       o1 += bias[32 + lane];
    o2 += bias[64 + lane];  o3 += bias[96 + lane];
    o0 = (o0 > 0.f) ? o0 : expm1f(o0);
    o1 = (o1 > 0.f) ? o1 : expm1f(o1);
    o2 = (o2 > 0.f) ? o2 : expm1f(o2);
    o3 = (o3 > 0.f) ? o3 : expm1f(o3);
    float* out = g_B + (size_t)n * 128;
    out[lane] = o0; out[32 + lane] = o1; out[64 + lane] = o2; out[96 + lane] = o3;
}

// ---------------- layer 3 GEMM (128->9, padded 12) fused with attn dots ----------------
__global__ void gemm3_kernel(const float* __restrict__ W3, const float* __restrict__ as3,
                             const float* __restrict__ ad3) {
    __shared__ float Ws[128 * 12];
    int t = threadIdx.x;   // 256
    for (int i = t; i < 128 * 12; i += 256) {
        int k = i / 12, c = i % 12;
        Ws[i] = (c < NCLS) ? W3[k * NCLS + c] : 0.f;
    }
    __syncthreads();
    int warp = t >> 5, lane = t & 31;
    int n = blockIdx.x * 8 + warp;
    if (n >= N_NODES) return;
    float acc[12];
    #pragma unroll
    for (int c = 0; c < 12; c++) acc[c] = 0.f;
    const float* xr = g_B + (size_t)n * 128;
    #pragma unroll
    for (int kk = 0; kk < 4; kk++) {
        int k = lane + kk * 32;
        float xv = xr[k];
        #pragma unroll
        for (int c = 0; c < 12; c++) acc[c] += xv * Ws[k * 12 + c];
    }
    #pragma unroll
    for (int off = 16; off; off >>= 1)
        #pragma unroll
        for (int c = 0; c < 12; c++) acc[c] += __shfl_xor_sync(0xffffffffu, acc[c], off);
    if (lane == 0) {
        float s = 0.f, d = 0.f;
        #pragma unroll
        for (int c = 0; c < NCLS; c++) { s += acc[c] * as3[c]; d += acc[c] * ad3[c]; }
        g_a3s[n] = s;
        g_a3d[n] = d;
        float* hr = g_h3 + (size_t)n * 12;
        #pragma unroll
        for (int c = 0; c < 12; c++) hr[c] = acc[c];
    }
}

// ---------------- layer 3 aggregation + bias + elu + log_softmax ----------------
__global__ void agg3_kernel(const float* __restrict__ b3, float* __restrict__ out) {
    int t = threadIdx.x;
    int warp = t >> 5, lane = t & 31;
    int n = blockIdx.x * 8 + warp;
    if (n >= N_NODES) return;
    int s0 = g_rowstart[n], s1 = g_rowstart[n + 1];
    float4 A0 = make_float4(0, 0, 0, 0), A1 = A0, A2 = A0;
    float ws = 0.f;
    for (int i = s0 + lane; i < s1; i += 32) {
        int s = g_adj_src[i];
        float w = g_w3[i];
        ws += w;
        const float4* r = (const float4*)(g_h3 + (size_t)s * 12);
        float4 r0 = r[0], r1 = r[1], r2 = r[2];
        A0.x += w * r0.x; A0.y += w * r0.y; A0.z += w * r0.z; A0.w += w * r0.w;
        A1.x += w * r1.x; A1.y += w * r1.y; A1.z += w * r1.z; A1.w += w * r1.w;
        A2.x += w * r2.x;
    }
    #pragma unroll
    for (int off = 16; off; off >>= 1) {
        A0.x += __shfl_xor_sync(0xffffffffu, A0.x, off);
        A0.y += __shfl_xor_sync(0xffffffffu, A0.y, off);
        A0.z += __shfl_xor_sync(0xffffffffu, A0.z, off);
        A0.w += __shfl_xor_sync(0xffffffffu, A0.w, off);
        A1.x += __shfl_xor_sync(0xffffffffu, A1.x, off);
        A1.y += __shfl_xor_sync(0xffffffffu, A1.y, off);
        A1.z += __shfl_xor_sync(0xffffffffu, A1.z, off);
        A1.w += __shfl_xor_sync(0xffffffffu, A1.w, off);
        A2.x += __shfl_xor_sync(0xffffffffu, A2.x, off);
        ws += __shfl_xor_sync(0xffffffffu, ws, off);
    }
    if (lane == 0) {
        float inv = (ws > 0.f) ? 1.f / ws : 0.f;
        float v[9];
        v[0] = A0.x * inv; v[1] = A0.y * inv; v[2] = A0.z * inv; v[3] = A0.w * inv;
        v[4] = A1.x * inv; v[5] = A1.y * inv; v[6] = A1.z * inv; v[7] = A1.w * inv;
        v[8] = A2.x * inv;
        float m = -1e30f;
        #pragma unroll
        for (int c = 0; c < 9; c++) {
            v[c] += b3[c];
            v[c] = (v[c] > 0.f) ? v[c] : expm1f(v[c]);
            m = fmaxf(m, v[c]);
        }
        float se = 0.f;
        #pragma unroll
        for (int c = 0; c < 9; c++) se += __expf(v[c] - m);
        float l = logf(se);
        float* o = out + (size_t)n * 9;
        #pragma unroll
        for (int c = 0; c < 9; c++) o[c] = v[c] - m - l;
    }
}

// ---------------- launch ----------------
extern "C" void kernel_launch(void* const* d_in, const int* in_sizes, int n_in,
                              void* d_out, int out_size) {
    const float* x   = (const float*)d_in[0];
    const void*  ei  = d_in[1];
    const float* W1  = (const float*)d_in[2];
    const float* as1 = (const float*)d_in[3];
    const float* ad1 = (const float*)d_in[4];
    const float* b1  = (const float*)d_in[5];
    const float* W2  = (const float*)d_in[6];
    const float* as2 = (const float*)d_in[7];
    const float* ad2 = (const float*)d_in[8];
    const float* b2  = (const float*)d_in[9];
    const float* W3  = (const float*)d_in[10];
    const float* as3 = (const float*)d_in[11];
    const float* ad3 = (const float*)d_in[12];
    const float* b3  = (const float*)d_in[13];
    float* out = (float*)d_out;

    const int EB = (N_EDGES + 255) / 256;
    const int WB = (N_NODES + 7) / 8;        // warp-per-node grids
    const int GB = (N_NODES + 127) / 128;    // gemm tiles (128 rows)

    // CSR build
    zero_kernel<<<SCAN_NB, 256>>>(ei);
    count_kernel<<<EB, 256>>>(ei);
    scanA_kernel<<<SCAN_NB, SCAN_B>>>();
    scanB_kernel<<<1, 256>>>();
    scanC_kernel<<<SCAN_NB, SCAN_B>>>();
    fill_kernel<<<EB, 256>>>(ei);

    // layer 1
    gemm_tf32_kernel<<<GB, 256>>>(x, W1, N_NODES, F_IN, as1, ad1);
    weight_kernel<<<EB, 256>>>();
    agg128_kernel<<<WB, 256>>>(b1);

    // layer 2
    gemm_tf32_kernel<<<GB, 256>>>(nullptr, W2, N_NODES, HID, as2, ad2);
    weight_kernel<<<EB, 256>>>();
    agg128_kernel<<<WB, 256>>>(b2);

    // layer 3
    gemm3_kernel<<<WB, 256>>>(W3, as3, ad3);
    weight3_kernel<<<EB, 256>>>();
    agg3_kernel<<<WB, 256>>>(b3, out);
}